// round 8
// baseline (speedup 1.0000x reference)
#include <cuda_runtime.h>
#include <cstdint>
#include <cstddef>

#define BATCH 64
#define CIN   64
#define COUT  64
#define MODES 16
#define NRES  8192
#define NH    4096   // NRES/2
#define NQ    2048   // NRES/4 — quarter-symmetry-reduced n range

typedef unsigned long long u64;

// Persistent device scratch (allocation-free rule: __device__ globals)
// Twiddles for n in [0,2048], modes EVEN/ODD-reordered:
//   slot s<8 -> m=2s, s>=8 -> m=2(s-8)+1. Each = (cos(2*pi*m*n/N), -sin(...)).
__device__ __align__(16) float2 g_tw[2080][MODES];          // ~266 KB, L2-resident
__device__ __align__(16) float2 g_Xp[8][BATCH][CIN][MODES]; // fwd n-partials, 4 MB
__device__ __align__(16) float2 g_Y [BATCH][COUT][MODES];   // mixed+scaled, slot order

// ---- packed f32x2 helpers (sm_100+) ----
__device__ __forceinline__ void ffma2(u64 &d, u64 a, u64 b) {
    asm("fma.rn.f32x2 %0, %1, %2, %0;" : "+l"(d) : "l"(a), "l"(b));
}
__device__ __forceinline__ void fadd2(u64 &d, u64 a) {
    asm("add.rn.f32x2 %0, %0, %1;" : "+l"(d) : "l"(a));
}
__device__ __forceinline__ u64 pk2(float lo, float hi) {
    u64 r; asm("mov.b64 %0, {%1, %2};" : "=l"(r) : "f"(lo), "f"(hi)); return r;
}
__device__ __forceinline__ void upk2(u64 v, float &lo, float &hi) {
    asm("mov.b64 {%0, %1}, %2;" : "=f"(lo), "=f"(hi) : "l"(v));
}
__device__ __forceinline__ int mslot(int m) { return ((m & 1) << 3) | (m >> 1); }

// ------------------------------------------------------------------
// Kernel 1: twiddle table, n in [0,2048].
// ------------------------------------------------------------------
__global__ void tw_kernel() {
    int idx = blockIdx.x * blockDim.x + threadIdx.x;
    if (idx >= 2049 * 16) return;
    int n = idx >> 4, m = idx & 15;
    int r = (n * m) & (NRES - 1);
    float s, c;
    sincospif((float)r * (1.0f / NH), &s, &c);
    g_tw[n][mslot(m)] = make_float2(c, -s);
}

// ------------------------------------------------------------------
// Kernel 2: quarter-folded forward DFT.
// Grid 512 = (b:64, q:8). Block 256 thr = 8 warps, all 64 i per warp
// (lane = i and i+32). Staged n in [q*256, q*256+256), 8 chunks of 32.
// Even modes consume pe=(u+u', u-u'); odd consume po=(v-v', v+v'),
// where primes are the 4096-n mirror. One ffma2 = both complex parts.
// ------------------------------------------------------------------
__global__ void __launch_bounds__(256, 2) fwd_kernel(const float* __restrict__ x) {
    __shared__ __align__(16) float4 uvq[64][33];   // (pe.x,pe.y,po.x,po.y), 33.8 KB
    __shared__ __align__(16) u64 tws[32][16];      // chunk twiddles, 4 KB

    int b = blockIdx.x >> 3, q = blockIdx.x & 7;
    int tid = threadIdx.x, w = tid >> 5, l = tid & 31;
    const float* xb = x + (size_t)b * CIN * NRES;

    u64 acc[32];                                   // [0..15]: i=l, [16..31]: i=l+32
    #pragma unroll
    for (int s = 0; s < 32; ++s) acc[s] = 0ull;

    float4 F[2], Bv[2], T;
    float RL[2][4], RH[2][4];

    // prefetch chunk 0
    {
        int nb = q << 8;
        int M = NH - nb;
        #pragma unroll
        for (int k = 0; k < 2; ++k) {
            int idx = k * 256 + tid, row = idx >> 3, c4 = idx & 7;
            const float* p = xb + (size_t)row * NRES + nb + (c4 << 2);
            F[k]  = *(const float4*)p;
            Bv[k] = *(const float4*)(p + NH);
            const float* pr = xb + (size_t)row * NRES;
            #pragma unroll
            for (int j = 0; j < 4; ++j) {
                int ridx = M - (c4 << 2) - j;
                bool ok = (ridx < NH);             // ridx==4096 (nb=0,c=0) -> self-pair, zero
                RL[k][j] = ok ? pr[ridx]      : 0.0f;
                RH[k][j] = ok ? pr[ridx + NH] : 0.0f;
            }
        }
        T = ((const float4*)&g_tw[nb][0])[tid];
    }

    for (int ch = 0; ch < 8; ++ch) {
        // store phase: fold into pe/po
        #pragma unroll
        for (int k = 0; k < 2; ++k) {
            int idx = k * 256 + tid, row = idx >> 3, c4 = idx & 7;
            float a0[4] = {F[k].x, F[k].y, F[k].z, F[k].w};
            float b0[4] = {Bv[k].x, Bv[k].y, Bv[k].z, Bv[k].w};
            #pragma unroll
            for (int j = 0; j < 4; ++j) {
                float u  = a0[j] + b0[j],     v  = a0[j] - b0[j];
                float up = RL[k][j] + RH[k][j], vp = RL[k][j] - RH[k][j];
                uvq[row][(c4 << 2) + j] = make_float4(u + up, u - up, v - vp, v + vp);
            }
        }
        ((float4*)tws)[tid] = T;
        __syncthreads();
        // prefetch next chunk
        if (ch < 7) {
            int nb = (q << 8) + ((ch + 1) << 5);
            int M = NH - nb;
            #pragma unroll
            for (int k = 0; k < 2; ++k) {
                int idx = k * 256 + tid, row = idx >> 3, c4 = idx & 7;
                const float* p = xb + (size_t)row * NRES + nb + (c4 << 2);
                F[k]  = *(const float4*)p;
                Bv[k] = *(const float4*)(p + NH);
                const float* pr = xb + (size_t)row * NRES;
                #pragma unroll
                for (int j = 0; j < 4; ++j) {
                    int ridx = M - (c4 << 2) - j;
                    RL[k][j] = pr[ridx];
                    RH[k][j] = pr[ridx + NH];
                }
            }
            T = ((const float4*)&g_tw[nb][0])[tid];
        }
        // compute: warp w covers 4 staged n; lanes = 32 i, each lane i and i+32
        #pragma unroll
        for (int j = 0; j < 4; ++j) {
            int c = (w << 2) + j;
            float4 q0 = uvq[l][c], q1 = uvq[l + 32][c];
            u64 pe0 = pk2(q0.x, q0.y), po0 = pk2(q0.z, q0.w);
            u64 pe1 = pk2(q1.x, q1.y), po1 = pk2(q1.z, q1.w);
            const ulonglong2* tp = (const ulonglong2*)&tws[c][0];
            #pragma unroll
            for (int m2 = 0; m2 < 4; ++m2) {       // even slots
                ulonglong2 t = tp[m2];
                ffma2(acc[2 * m2],      t.x, pe0);
                ffma2(acc[2 * m2 + 1],  t.y, pe0);
                ffma2(acc[16 + 2 * m2], t.x, pe1);
                ffma2(acc[17 + 2 * m2], t.y, pe1);
            }
            #pragma unroll
            for (int m2 = 4; m2 < 8; ++m2) {       // odd slots
                ulonglong2 t = tp[m2];
                ffma2(acc[2 * m2],      t.x, po0);
                ffma2(acc[2 * m2 + 1],  t.y, po0);
                ffma2(acc[16 + 2 * m2], t.x, po1);
                ffma2(acc[17 + 2 * m2], t.y, po1);
            }
        }
        __syncthreads();
    }

    // self-paired n=2048 contribution (added once, by warp 0 of q==0 blocks)
    if (q == 0 && w == 0) {
        const float* p0 = xb + (size_t)l * NRES;
        const float* p1 = xb + (size_t)(l + 32) * NRES;
        float u0 = p0[NQ] + p0[NQ + NH], v0 = p0[NQ] - p0[NQ + NH];
        float u1 = p1[NQ] + p1[NQ + NH], v1 = p1[NQ] - p1[NQ + NH];
        u64 pe0 = pk2(u0, u0), po0 = pk2(v0, v0);
        u64 pe1 = pk2(u1, u1), po1 = pk2(v1, v1);
        const ulonglong2* tp = (const ulonglong2*)&g_tw[NQ][0];
        #pragma unroll
        for (int m2 = 0; m2 < 4; ++m2) {
            ulonglong2 t = tp[m2];
            ffma2(acc[2 * m2],      t.x, pe0); ffma2(acc[2 * m2 + 1],  t.y, pe0);
            ffma2(acc[16 + 2 * m2], t.x, pe1); ffma2(acc[17 + 2 * m2], t.y, pe1);
        }
        #pragma unroll
        for (int m2 = 4; m2 < 8; ++m2) {
            ulonglong2 t = tp[m2];
            ffma2(acc[2 * m2],      t.x, po0); ffma2(acc[2 * m2 + 1],  t.y, po0);
            ffma2(acc[16 + 2 * m2], t.x, po1); ffma2(acc[17 + 2 * m2], t.y, po1);
        }
    }

    // cross-warp tree reduction, two 16-acc phases (reuses uvq, 16 KB)
    u64* red = (u64*)uvq;
    #pragma unroll
    for (int g = 0; g < 32; g += 16) {
        for (int half = 4; half > 0; half >>= 1) {
            if (w >= half && w < (half << 1)) {
                #pragma unroll
                for (int m = 0; m < 16; ++m)
                    red[((((w - half) << 4) + m) << 5) + l] = acc[g + m];
            }
            __syncthreads();
            if (w < half) {
                #pragma unroll
                for (int m = 0; m < 16; ++m)
                    fadd2(acc[g + m], red[(((w << 4) + m) << 5) + l]);
            }
            __syncthreads();
        }
    }
    if (w == 0) {
        u64* Xp = (u64*)&g_Xp[q][b][0][0];
        #pragma unroll
        for (int m = 0; m < 16; ++m) {
            Xp[l * 16 + m]        = acc[m];
            Xp[(l + 32) * 16 + m] = acc[16 + m];
        }
    }
}

// ------------------------------------------------------------------
// Kernel 3: sum 8 fwd partials + complex mode mix + irfft scale.
// ------------------------------------------------------------------
__global__ void __launch_bounds__(512) mix_kernel(const float* __restrict__ wr,
                                                  const float* __restrict__ wi) {
    __shared__ __align__(16) float2 Xs[CIN][MODES];   // 8 KB, slot order
    int b = blockIdx.x >> 1, oh = blockIdx.x & 1;
    int tid = threadIdx.x;
    const int STRIDE = BATCH * CIN * MODES;
    for (int t = tid; t < CIN * MODES; t += 512) {
        const float2* p = &((const float2*)g_Xp)[(size_t)b * CIN * MODES + t];
        float sx = 0.f, sy = 0.f;
        #pragma unroll
        for (int k = 0; k < 8; ++k) {
            float2 a = p[(size_t)k * STRIDE];
            sx += a.x; sy += a.y;
        }
        ((float2*)Xs)[t] = make_float2(sx, sy);
    }
    __syncthreads();
    int o = (oh << 5) + (tid >> 4), m = tid & 15, s = mslot(m);
    float yr = 0.f, yi = 0.f;
    #pragma unroll 4
    for (int i = 0; i < CIN; ++i) {
        float2 xv = Xs[i][s];
        float a = wr[(i * COUT + o) * MODES + m];
        float c = wi[(i * COUT + o) * MODES + m];
        yr = fmaf(xv.x, a, yr); yr = fmaf(-xv.y, c, yr);
        yi = fmaf(xv.x, c, yi); yi = fmaf(xv.y, a, yi);
    }
    float sc = (m == 0 ? 1.0f : 2.0f) * (1.0f / NRES);
    g_Y[b][o][s] = make_float2(yr * sc, yi * sc);
}

// ------------------------------------------------------------------
// Kernel 4: quarter-folded inverse.
// Grid 1024 = (b:64, q:16), block 128. Thread owns one n in [0,2048):
// 16 twiddle u64 in regs; 16 ffma2 per o emit FOUR outputs:
//   e=(Pe,Qe), od=(Po,Qo);  out[n]=Pe+Qe+Po+Qo, out[n+4096]=Pe+Qe-Po-Qo,
//   out[4096-n]=(Pe-Qe)+(Qo-Po), out[8192-n]=(Pe-Qe)-(Qo-Po).
// ------------------------------------------------------------------
__global__ void __launch_bounds__(128, 6) inv_kernel(float* __restrict__ out) {
    __shared__ __align__(16) u64 Ysh[COUT][MODES];   // 8 KB, slot order
    int b = blockIdx.x >> 4, q = blockIdx.x & 15;
    int tid = threadIdx.x;
    const u64* Yg = (const u64*)g_Y + (size_t)b * COUT * MODES;
    #pragma unroll
    for (int k = 0; k < 8; ++k) ((u64*)Ysh)[tid + k * 128] = Yg[tid + k * 128];
    __syncthreads();

    int n = (q << 7) + tid;
    u64 tw[16];
    {
        const ulonglong2* tp = (const ulonglong2*)&g_tw[n][0];
        #pragma unroll
        for (int m2 = 0; m2 < 8; ++m2) {
            ulonglong2 t = tp[m2];
            tw[2 * m2] = t.x; tw[2 * m2 + 1] = t.y;
        }
    }
    float* pb = out + (size_t)b * COUT * NRES;

    #pragma unroll 2
    for (int o = 0; o < COUT; ++o) {
        const ulonglong2* yp = (const ulonglong2*)&Ysh[o][0];
        u64 e = 0ull, od = 0ull;
        #pragma unroll
        for (int m2 = 0; m2 < 4; ++m2) {             // even slots
            ulonglong2 y = yp[m2];
            ffma2(e, y.x, tw[2 * m2]); ffma2(e, y.y, tw[2 * m2 + 1]);
        }
        #pragma unroll
        for (int m2 = 4; m2 < 8; ++m2) {             // odd slots
            ulonglong2 y = yp[m2];
            ffma2(od, y.x, tw[2 * m2]); ffma2(od, y.y, tw[2 * m2 + 1]);
        }
        float pe, qe, po, qo;
        upk2(e, pe, qe); upk2(od, po, qo);
        float S = pe + qe, D = pe - qe, Tm = po + qo, U = qo - po;
        float* p = pb + (size_t)o * NRES;
        p[n]      = S + Tm;
        p[n + NH] = S - Tm;
        if (n) {
            p[NH - n]   = D + U;
            p[NRES - n] = D - U;
        }
    }

    // self-paired n=2048 outputs (out[2048], out[6144]) — q==0, one o per thread
    if (q == 0 && tid < COUT) {
        int o = tid;
        const ulonglong2* tp = (const ulonglong2*)&g_tw[NQ][0];
        const ulonglong2* yp = (const ulonglong2*)&Ysh[o][0];
        u64 e = 0ull, od = 0ull;
        #pragma unroll
        for (int m2 = 0; m2 < 4; ++m2) {
            ulonglong2 t = tp[m2]; ulonglong2 y = yp[m2];
            ffma2(e, y.x, t.x); ffma2(e, y.y, t.y);
        }
        #pragma unroll
        for (int m2 = 4; m2 < 8; ++m2) {
            ulonglong2 t = tp[m2]; ulonglong2 y = yp[m2];
            ffma2(od, y.x, t.x); ffma2(od, y.y, t.y);
        }
        float pe, qe, po, qo;
        upk2(e, pe, qe); upk2(od, po, qo);
        float E = pe + qe, O = po + qo;
        float* p = pb + (size_t)o * NRES;
        p[NQ]          = E + O;
        p[NQ + NH]     = E - O;
    }
}

// ------------------------------------------------------------------
extern "C" void kernel_launch(void* const* d_in, const int* in_sizes, int n_in,
                              void* d_out, int out_size) {
    (void)in_sizes; (void)n_in; (void)out_size;
    const float* x  = (const float*)d_in[0];   // [64,64,8192]
    const float* wr = (const float*)d_in[1];   // [64,64,16]
    const float* wi = (const float*)d_in[2];   // [64,64,16]
    float* out = (float*)d_out;                // [64,64,8192]

    tw_kernel <<<129, 256>>>();
    fwd_kernel<<<512, 256>>>(x);
    mix_kernel<<<128, 512>>>(wr, wi);
    inv_kernel<<<1024, 128>>>(out);
}

// round 9
// speedup vs baseline: 1.1495x; 1.1495x over previous
#include <cuda_runtime.h>
#include <cstdint>
#include <cstddef>

#define BATCH 64
#define CIN   64
#define COUT  64
#define MODES 16
#define NRES  8192
#define NH    4096   // NRES/2
#define NQ    2048   // NRES/4 — quarter-symmetry-reduced n range

typedef unsigned long long u64;

// Persistent device scratch (allocation-free rule: __device__ globals)
// Twiddles for n in [0,2048], modes EVEN/ODD-reordered:
//   slot s<8 -> m=2s, s>=8 -> m=2(s-8)+1. Each = (cos(2*pi*m*n/N), -sin(...)).
__device__ __align__(16) float2 g_tw[2080][MODES];          // ~266 KB, L2-resident
__device__ __align__(16) float2 g_Xp[4][BATCH][CIN][MODES]; // fwd n-partials, 2 MB
__device__ __align__(16) float2 g_Y [BATCH][COUT][MODES];   // mixed+scaled, slot order

// ---- packed f32x2 helpers (sm_100+) ----
__device__ __forceinline__ void ffma2(u64 &d, u64 a, u64 b) {
    asm("fma.rn.f32x2 %0, %1, %2, %0;" : "+l"(d) : "l"(a), "l"(b));
}
__device__ __forceinline__ void fadd2(u64 &d, u64 a) {
    asm("add.rn.f32x2 %0, %0, %1;" : "+l"(d) : "l"(a));
}
__device__ __forceinline__ u64 pk2(float lo, float hi) {
    u64 r; asm("mov.b64 %0, {%1, %2};" : "=l"(r) : "f"(lo), "f"(hi)); return r;
}
__device__ __forceinline__ void upk2(u64 v, float &lo, float &hi) {
    asm("mov.b64 {%0, %1}, %2;" : "=f"(lo), "=f"(hi) : "l"(v));
}
__device__ __forceinline__ int mslot(int m) { return ((m & 1) << 3) | (m >> 1); }

// ---- cp.async helpers ----
__device__ __forceinline__ uint32_t sptr(const void* p) {
    return (uint32_t)__cvta_generic_to_shared(p);
}
__device__ __forceinline__ void cpa16(uint32_t dst, const void* src) {
    asm volatile("cp.async.cg.shared.global [%0], [%1], 16;" :: "r"(dst), "l"(src));
}
__device__ __forceinline__ void cpa_commit() {
    asm volatile("cp.async.commit_group;" ::: "memory");
}
__device__ __forceinline__ void cpa_wait0() {
    asm volatile("cp.async.wait_group 0;" ::: "memory");
}

// ------------------------------------------------------------------
// Kernel 1: twiddle table, n in [0,2048].
// ------------------------------------------------------------------
__global__ void tw_kernel() {
    int idx = blockIdx.x * blockDim.x + threadIdx.x;
    if (idx >= 2049 * 16) return;
    int n = idx >> 4, m = idx & 15;
    int r = (n * m) & (NRES - 1);
    float s, c;
    sincospif((float)r * (1.0f / NH), &s, &c);
    g_tw[n][mslot(m)] = make_float2(c, -s);
}

// ------------------------------------------------------------------
// Kernel 2: quarter-folded forward DFT, cp.async staged.
// Grid 256 = (b:64, q:4). Block 256 thr = 8 warps; 32 chunks of 16 staged n.
// Stage: A=x[nb..+16), B=A+NH, M=x[NH-nb-16..+20) (fwd-contig mirror), MB=M+NH.
// Fold (smem->smem): pe=(u+u', u-u'), po=(v-v', v+v') with mirror reversal
// done by INDEXING, not by gmem access pattern. Compute phase == round-8 math.
// No persistent register staging => no spills (~90 regs).
// ------------------------------------------------------------------
__global__ void __launch_bounds__(256, 2) fwd_kernel(const float* __restrict__ x) {
    __shared__ __align__(16) float  As [64][16];   // 4 KB
    __shared__ __align__(16) float  Bs [64][16];   // 4 KB
    __shared__ __align__(16) float  Ms [64][24];   // 6 KB (20 data floats/row)
    __shared__ __align__(16) float  MBs[64][24];   // 6 KB
    __shared__ __align__(16) u64    tws[2][16][16];// 4 KB double-buffered
    __shared__ __align__(16) float4 uvq[64][17];   // 17 KB (pe.x,pe.y,po.x,po.y)

    int b = blockIdx.x >> 2, q = blockIdx.x & 3;
    int tid = threadIdx.x, w = tid >> 5, l = tid & 31;
    const float* xb = x + (size_t)b * CIN * NRES;
    int base = q << 9;                             // 512 staged n per block

    u64 acc[32];                                   // [0..15]: i=l, [16..31]: i=l+32
    #pragma unroll
    for (int s = 0; s < 32; ++s) acc[s] = 0ull;

    // --- async stage of one chunk (issue only) ---
    auto stage = [&](int nb, int par) {
        {   // A, B: 64 rows x 4 units; unit = tid
            int row = tid >> 2, u4 = (tid & 3) << 2;
            const float* p = xb + (size_t)row * NRES + nb + u4;
            cpa16(sptr(&As[row][u4]), p);
            cpa16(sptr(&Bs[row][u4]), p + NH);
        }
        {   // M, MB: 64 rows x 5 units = 320 units
            int mbase = NH - nb - 16;
            for (int idx = tid; idx < 320; idx += 256) {
                int row = idx / 5, g4 = (idx % 5) << 2;
                const float* p = xb + (size_t)row * NRES + mbase + g4;
                cpa16(sptr(&Ms[row][g4]),  p);
                cpa16(sptr(&MBs[row][g4]), p + NH);
            }
        }
        if (tid < 128) {                           // tw chunk: 16 n x 128B
            int row = tid >> 3, u = tid & 7;
            cpa16(sptr((const char*)&tws[par][row][0] + (u << 4)),
                  (const char*)&g_tw[nb + row][0] + (u << 4));
        }
    };

    stage(base, 0);
    cpa_commit();

    for (int ch = 0; ch < 32; ++ch) {
        int nb = base + (ch << 4);
        cpa_wait0();
        __syncthreads();                           // raw chunk ch landed everywhere

        // fold: raw -> uvq (thread = (row, 4-col group))
        {
            int row = tid >> 2, c4 = (tid & 3) << 2;
            float4 a = *(const float4*)&As[row][c4];
            float4 bb = *(const float4*)&Bs[row][c4];
            float av[4] = {a.x, a.y, a.z, a.w};
            float bv[4] = {bb.x, bb.y, bb.z, bb.w};
            #pragma unroll
            for (int j = 0; j < 4; ++j) {
                int col = c4 + j;
                float m_  = Ms [row][16 - col];    // mirror via indexing
                float mb_ = MBs[row][16 - col];
                if (nb == 0 && col == 0) { m_ = 0.0f; mb_ = 0.0f; }  // n=0: no partner
                float u  = av[j] + bv[j], v  = av[j] - bv[j];
                float up = m_ + mb_,      vp = m_ - mb_;
                uvq[row][col] = make_float4(u + up, u - up, v - vp, v + vp);
            }
        }
        __syncthreads();                           // uvq ready; raw consumed

        if (ch < 31) {                             // overlap next copy with compute
            stage(nb + 16, (ch + 1) & 1);
            cpa_commit();
        }

        // compute: warp w covers staged cols {2w, 2w+1}; lanes = i and i+32
        int par = ch & 1;
        #pragma unroll
        for (int cc = 0; cc < 2; ++cc) {
            int c = (w << 1) | cc;
            float4 q0 = uvq[l][c], q1 = uvq[l + 32][c];
            u64 pe0 = pk2(q0.x, q0.y), po0 = pk2(q0.z, q0.w);
            u64 pe1 = pk2(q1.x, q1.y), po1 = pk2(q1.z, q1.w);
            const ulonglong2* tp = (const ulonglong2*)&tws[par][c][0];
            #pragma unroll
            for (int m2 = 0; m2 < 4; ++m2) {       // even slots
                ulonglong2 t = tp[m2];
                ffma2(acc[2 * m2],      t.x, pe0);
                ffma2(acc[2 * m2 + 1],  t.y, pe0);
                ffma2(acc[16 + 2 * m2], t.x, pe1);
                ffma2(acc[17 + 2 * m2], t.y, pe1);
            }
            #pragma unroll
            for (int m2 = 4; m2 < 8; ++m2) {       // odd slots
                ulonglong2 t = tp[m2];
                ffma2(acc[2 * m2],      t.x, po0);
                ffma2(acc[2 * m2 + 1],  t.y, po0);
                ffma2(acc[16 + 2 * m2], t.x, po1);
                ffma2(acc[17 + 2 * m2], t.y, po1);
            }
        }
        __syncthreads();                           // uvq free for next fold
    }

    // self-paired n=2048 contribution (added once, by warp 0 of q==0 blocks)
    if (q == 0 && w == 0) {
        const float* p0 = xb + (size_t)l * NRES;
        const float* p1 = xb + (size_t)(l + 32) * NRES;
        float u0 = p0[NQ] + p0[NQ + NH], v0 = p0[NQ] - p0[NQ + NH];
        float u1 = p1[NQ] + p1[NQ + NH], v1 = p1[NQ] - p1[NQ + NH];
        u64 pe0 = pk2(u0, u0), po0 = pk2(v0, v0);
        u64 pe1 = pk2(u1, u1), po1 = pk2(v1, v1);
        const ulonglong2* tp = (const ulonglong2*)&g_tw[NQ][0];
        #pragma unroll
        for (int m2 = 0; m2 < 4; ++m2) {
            ulonglong2 t = tp[m2];
            ffma2(acc[2 * m2],      t.x, pe0); ffma2(acc[2 * m2 + 1],  t.y, pe0);
            ffma2(acc[16 + 2 * m2], t.x, pe1); ffma2(acc[17 + 2 * m2], t.y, pe1);
        }
        #pragma unroll
        for (int m2 = 4; m2 < 8; ++m2) {
            ulonglong2 t = tp[m2];
            ffma2(acc[2 * m2],      t.x, po0); ffma2(acc[2 * m2 + 1],  t.y, po0);
            ffma2(acc[16 + 2 * m2], t.x, po1); ffma2(acc[17 + 2 * m2], t.y, po1);
        }
    }

    // cross-warp tree reduction, two 16-acc phases (reuses uvq, 16 KB)
    u64* red = (u64*)uvq;
    #pragma unroll
    for (int g = 0; g < 32; g += 16) {
        for (int half = 4; half > 0; half >>= 1) {
            if (w >= half && w < (half << 1)) {
                #pragma unroll
                for (int m = 0; m < 16; ++m)
                    red[((((w - half) << 4) + m) << 5) + l] = acc[g + m];
            }
            __syncthreads();
            if (w < half) {
                #pragma unroll
                for (int m = 0; m < 16; ++m)
                    fadd2(acc[g + m], red[(((w << 4) + m) << 5) + l]);
            }
            __syncthreads();
        }
    }
    if (w == 0) {
        u64* Xp = (u64*)&g_Xp[q][b][0][0];
        #pragma unroll
        for (int m = 0; m < 16; ++m) {
            Xp[l * 16 + m]        = acc[m];
            Xp[(l + 32) * 16 + m] = acc[16 + m];
        }
    }
}

// ------------------------------------------------------------------
// Kernel 3: sum 4 fwd partials + complex mode mix + irfft scale.
// ------------------------------------------------------------------
__global__ void __launch_bounds__(512) mix_kernel(const float* __restrict__ wr,
                                                  const float* __restrict__ wi) {
    __shared__ __align__(16) float2 Xs[CIN][MODES];   // 8 KB, slot order
    int b = blockIdx.x >> 1, oh = blockIdx.x & 1;
    int tid = threadIdx.x;
    const int STRIDE = BATCH * CIN * MODES;
    for (int t = tid; t < CIN * MODES; t += 512) {
        const float2* p = &((const float2*)g_Xp)[(size_t)b * CIN * MODES + t];
        float sx = 0.f, sy = 0.f;
        #pragma unroll
        for (int k = 0; k < 4; ++k) {
            float2 a = p[(size_t)k * STRIDE];
            sx += a.x; sy += a.y;
        }
        ((float2*)Xs)[t] = make_float2(sx, sy);
    }
    __syncthreads();
    int o = (oh << 5) + (tid >> 4), m = tid & 15, s = mslot(m);
    float yr = 0.f, yi = 0.f;
    #pragma unroll 4
    for (int i = 0; i < CIN; ++i) {
        float2 xv = Xs[i][s];
        float a = wr[(i * COUT + o) * MODES + m];
        float c = wi[(i * COUT + o) * MODES + m];
        yr = fmaf(xv.x, a, yr); yr = fmaf(-xv.y, c, yr);
        yi = fmaf(xv.x, c, yi); yi = fmaf(xv.y, a, yi);
    }
    float sc = (m == 0 ? 1.0f : 2.0f) * (1.0f / NRES);
    g_Y[b][o][s] = make_float2(yr * sc, yi * sc);
}

// ------------------------------------------------------------------
// Kernel 4: quarter-folded inverse (unchanged from round 8, 30.7us).
// ------------------------------------------------------------------
__global__ void __launch_bounds__(128, 6) inv_kernel(float* __restrict__ out) {
    __shared__ __align__(16) u64 Ysh[COUT][MODES];   // 8 KB, slot order
    int b = blockIdx.x >> 4, q = blockIdx.x & 15;
    int tid = threadIdx.x;
    const u64* Yg = (const u64*)g_Y + (size_t)b * COUT * MODES;
    #pragma unroll
    for (int k = 0; k < 8; ++k) ((u64*)Ysh)[tid + k * 128] = Yg[tid + k * 128];
    __syncthreads();

    int n = (q << 7) + tid;
    u64 tw[16];
    {
        const ulonglong2* tp = (const ulonglong2*)&g_tw[n][0];
        #pragma unroll
        for (int m2 = 0; m2 < 8; ++m2) {
            ulonglong2 t = tp[m2];
            tw[2 * m2] = t.x; tw[2 * m2 + 1] = t.y;
        }
    }
    float* pb = out + (size_t)b * COUT * NRES;

    #pragma unroll 2
    for (int o = 0; o < COUT; ++o) {
        const ulonglong2* yp = (const ulonglong2*)&Ysh[o][0];
        u64 e = 0ull, od = 0ull;
        #pragma unroll
        for (int m2 = 0; m2 < 4; ++m2) {             // even slots
            ulonglong2 y = yp[m2];
            ffma2(e, y.x, tw[2 * m2]); ffma2(e, y.y, tw[2 * m2 + 1]);
        }
        #pragma unroll
        for (int m2 = 4; m2 < 8; ++m2) {             // odd slots
            ulonglong2 y = yp[m2];
            ffma2(od, y.x, tw[2 * m2]); ffma2(od, y.y, tw[2 * m2 + 1]);
        }
        float pe, qe, po, qo;
        upk2(e, pe, qe); upk2(od, po, qo);
        float S = pe + qe, D = pe - qe, Tm = po + qo, U = qo - po;
        float* p = pb + (size_t)o * NRES;
        p[n]      = S + Tm;
        p[n + NH] = S - Tm;
        if (n) {
            p[NH - n]   = D + U;
            p[NRES - n] = D - U;
        }
    }

    // self-paired n=2048 outputs — q==0, one o per thread
    if (q == 0 && tid < COUT) {
        int o = tid;
        const ulonglong2* tp = (const ulonglong2*)&g_tw[NQ][0];
        const ulonglong2* yp = (const ulonglong2*)&Ysh[o][0];
        u64 e = 0ull, od = 0ull;
        #pragma unroll
        for (int m2 = 0; m2 < 4; ++m2) {
            ulonglong2 t = tp[m2]; ulonglong2 y = yp[m2];
            ffma2(e, y.x, t.x); ffma2(e, y.y, t.y);
        }
        #pragma unroll
        for (int m2 = 4; m2 < 8; ++m2) {
            ulonglong2 t = tp[m2]; ulonglong2 y = yp[m2];
            ffma2(od, y.x, t.x); ffma2(od, y.y, t.y);
        }
        float pe, qe, po, qo;
        upk2(e, pe, qe); upk2(od, po, qo);
        float E = pe + qe, O = po + qo;
        float* p = pb + (size_t)o * NRES;
        p[NQ]      = E + O;
        p[NQ + NH] = E - O;
    }
}

// ------------------------------------------------------------------
extern "C" void kernel_launch(void* const* d_in, const int* in_sizes, int n_in,
                              void* d_out, int out_size) {
    (void)in_sizes; (void)n_in; (void)out_size;
    const float* x  = (const float*)d_in[0];   // [64,64,8192]
    const float* wr = (const float*)d_in[1];   // [64,64,16]
    const float* wi = (const float*)d_in[2];   // [64,64,16]
    float* out = (float*)d_out;                // [64,64,8192]

    tw_kernel <<<129, 256>>>();
    fwd_kernel<<<256, 256>>>(x);
    mix_kernel<<<128, 512>>>(wr, wi);
    inv_kernel<<<1024, 128>>>(out);
}